// round 16
// baseline (speedup 1.0000x reference)
#include <cuda_runtime.h>
#include <cstdint>

#define NUM_B  4
#define SEQ    2048
#define DMODEL 1024
#define NH     16
#define DHEAD  64
#define MTOT   (NUM_B * SEQ)   // 8192

// ---------------------------------------------------------------------------
// Scratch (__device__ globals). All tf32-pre-rounded AND k-dim pre-permuted
// (within each 16-chunk: pos p holds k = perm(p), perm(p)=((p&3)<<2)|(p>>2)).
// Gmem is byte-identical to the smem tile layout -> staging is cp.async 16B.
// ---------------------------------------------------------------------------
__device__ float    g_q   [(size_t)NUM_B * NH * SEQ * DHEAD];  // [bh][s][d~] (x 0.125*log2e)
__device__ float    g_k   [(size_t)NUM_B * NH * SEQ * DHEAD];  // [bh][s][d~]
__device__ float    g_vt  [(size_t)NUM_B * NH * DHEAD * SEQ];  // [bh][d][s~]
__device__ float    g_attn[(size_t)NUM_B * SEQ * DMODEL];      // [b][s][D~]
__device__ float    g_wt  [4ull * DMODEL * DMODEL];            // Wt[z][n][k~]
__device__ float    g_x   [3ull * MTOT * DMODEL];              // x rounded+perm
__device__ uint32_t g_mbits[(size_t)NUM_B * SEQ * (SEQ / 32)]; // bit-packed mask

// ---------------------------------------------------------------------------
__device__ __forceinline__ float tf32r(float x) {
    uint32_t u;
    asm("cvt.rna.tf32.f32 %0, %1;" : "=r"(u) : "f"(x));
    return __uint_as_float(u);
}
__device__ __forceinline__ float ex2f(float x) {
    float r;
    asm("ex2.approx.ftz.f32 %0, %1;" : "=f"(r) : "f"(x));
    return r;
}
__device__ __forceinline__ int perm16(int v) { return ((v & 3) << 2) | (v >> 2); }

__device__ __forceinline__ void mma_tf32(float c[4], const float a[4], const float b[2]) {
    const uint32_t* A = reinterpret_cast<const uint32_t*>(a);
    const uint32_t* B = reinterpret_cast<const uint32_t*>(b);
    asm volatile(
        "mma.sync.aligned.m16n8k8.row.col.f32.tf32.tf32.f32 "
        "{%0,%1,%2,%3},{%4,%5,%6,%7},{%8,%9},{%0,%1,%2,%3};\n"
        : "+f"(c[0]), "+f"(c[1]), "+f"(c[2]), "+f"(c[3])
        : "r"(A[0]), "r"(A[1]), "r"(A[2]), "r"(A[3]), "r"(B[0]), "r"(B[1]));
}

__device__ __forceinline__ uint32_t smem_u32(const void* p) {
    return (uint32_t)__cvta_generic_to_shared(p);
}
__device__ __forceinline__ void cp16(uint32_t dst, const void* src) {
    asm volatile("cp.async.cg.shared.global [%0], [%1], 16;" :: "r"(dst), "l"(src));
}
#define CP_COMMIT() asm volatile("cp.async.commit_group;" ::: "memory")
#define CP_WAIT1()  asm volatile("cp.async.wait_group 1;" ::: "memory")
#define CP_WAIT0()  asm volatile("cp.async.wait_group 0;" ::: "memory")

// ---------------------------------------------------------------------------
// Pack mask to bits: word widx covers ints [widx*32, widx*32+32).
// Each thread consumes exactly one 128-B line. grid 2048, block 256.
// ---------------------------------------------------------------------------
__global__ void pack_mask(const int* __restrict__ mask)
{
    const size_t widx = (size_t)blockIdx.x * blockDim.x + threadIdx.x;
    const int4* src = (const int4*)mask + widx * 8;
    uint32_t w = 0;
#pragma unroll
    for (int r = 0; r < 8; r++) {
        const int4 v = src[r];
        w |= (v.x != 0 ? 1u : 0u) << (r * 4 + 0);
        w |= (v.y != 0 ? 1u : 0u) << (r * 4 + 1);
        w |= (v.z != 0 ? 1u : 0u) << (r * 4 + 2);
        w |= (v.w != 0 ? 1u : 0u) << (r * 4 + 3);
    }
    g_mbits[widx] = w;
}

// ---------------------------------------------------------------------------
// Pre-round + permute inputs: per 16-chunk transpose of 4 float4s.
// ---------------------------------------------------------------------------
__global__ void round_perm_x(const float* __restrict__ xq,
                             const float* __restrict__ xk,
                             const float* __restrict__ xv)
{
    const int z = blockIdx.y;
    const float* src = (z == 0) ? xq : (z == 1) ? xk : xv;
    float* dst = g_x + (size_t)z * MTOT * DMODEL;
    const size_t chunk = (size_t)blockIdx.x * blockDim.x + threadIdx.x;
    const float4* s = (const float4*)src + chunk * 4;
    float4 i0 = s[0], i1 = s[1], i2 = s[2], i3 = s[3];
    float4* d = (float4*)dst + chunk * 4;
    d[0] = make_float4(tf32r(i0.x), tf32r(i1.x), tf32r(i2.x), tf32r(i3.x));
    d[1] = make_float4(tf32r(i0.y), tf32r(i1.y), tf32r(i2.y), tf32r(i3.y));
    d[2] = make_float4(tf32r(i0.z), tf32r(i1.z), tf32r(i2.z), tf32r(i3.z));
    d[3] = make_float4(tf32r(i0.w), tf32r(i1.w), tf32r(i2.w), tf32r(i3.w));
}

// ---------------------------------------------------------------------------
// Weight transpose + round + k-permute.
// ---------------------------------------------------------------------------
__global__ void transpose_weights(const float* __restrict__ Wq, const float* __restrict__ Wk,
                                  const float* __restrict__ Wv, const float* __restrict__ Wo)
{
    __shared__ float tile[32][33];
    const float* W = (blockIdx.z == 0) ? Wq : (blockIdx.z == 1) ? Wk
                   : (blockIdx.z == 2) ? Wv : Wo;
    float* Wt = g_wt + (size_t)blockIdx.z * DMODEL * DMODEL;
    const int x0 = blockIdx.x * 32, y0 = blockIdx.y * 32;
    const int tx = threadIdx.x, ty = threadIdx.y;
#pragma unroll
    for (int r = 0; r < 32; r += 8)
        tile[ty + r][tx] = W[(size_t)(y0 + ty + r) * DMODEL + x0 + tx];
    __syncthreads();
    const int kl = (tx & ~15) | perm16(tx & 15);
#pragma unroll
    for (int r = 0; r < 32; r += 8)
        Wt[(size_t)(x0 + ty + r) * DMODEL + y0 + tx] = tf32r(tile[kl][ty + r]);
}

// ---------------------------------------------------------------------------
// tf32 GEMM mainloop (cp.async, double-buffered). Proven from R14/R15.
// ---------------------------------------------------------------------------
#define GEMM_SMEM_BYTES (2 * 2 * 256 * 24 * 4)   // 98304

__device__ __forceinline__ void gemm_tc_body(
    const float* __restrict__ Ablk, const float* __restrict__ Btblk,
    float* sm, float (&acc)[2][8][4])
{
    const int t = threadIdx.x, lane = t & 31, wid = t >> 5;
    const int gid = lane >> 2, tig = lane & 3;
    const int wM = wid >> 1, wN = wid & 1;

    auto stage = [&](int k0, int buf) {
        float* As = sm + buf * 12288;
        float* Bs = As + 6144;
#pragma unroll
        for (int r = 0; r < 4; r++) {
            const int i = t + r * 256;
            const int m = i >> 3, kq = i & 7;
            const int off = (m * 2 + (kq >> 2)) * 24 + (kq & 3) * 4;
            cp16(smem_u32(As + off), Ablk  + (size_t)m * DMODEL + k0 + kq * 4);
            cp16(smem_u32(Bs + off), Btblk + (size_t)m * DMODEL + k0 + kq * 4);
        }
        CP_COMMIT();
    };
    stage(0, 0);

    for (int k0 = 0; k0 < DMODEL; k0 += 32) {
        const int buf = (k0 >> 5) & 1;
        if (k0 + 32 < DMODEL) { stage(k0 + 32, buf ^ 1); CP_WAIT1(); }
        else                  { CP_WAIT0(); }
        __syncthreads();

        float* As = sm + buf * 12288;
        float* Bs = As + 6144;
#pragma unroll
        for (int g = 0; g < 2; g++) {
            float4 alo[2], ahi[2], bf[8];
#pragma unroll
            for (int mi = 0; mi < 2; mi++) {
                const int r0 = wM * 32 + mi * 16 + gid;
                alo[mi] = *(const float4*)(As + (r0 * 2 + g) * 24 + tig * 4);
                ahi[mi] = *(const float4*)(As + ((r0 + 8) * 2 + g) * 24 + tig * 4);
            }
#pragma unroll
            for (int ni = 0; ni < 8; ni++) {
                const int n = wN * 64 + ni * 8 + gid;
                bf[ni] = *(const float4*)(Bs + (n * 2 + g) * 24 + tig * 4);
            }
#pragma unroll
            for (int s = 0; s < 2; s++) {
                float a[2][4];
#pragma unroll
                for (int mi = 0; mi < 2; mi++) {
                    a[mi][0] = s ? alo[mi].z : alo[mi].x;
                    a[mi][1] = s ? ahi[mi].z : ahi[mi].x;
                    a[mi][2] = s ? alo[mi].w : alo[mi].y;
                    a[mi][3] = s ? ahi[mi].w : ahi[mi].y;
                }
#pragma unroll
                for (int ni = 0; ni < 8; ni++) {
                    float b2[2];
                    b2[0] = s ? bf[ni].z : bf[ni].x;
                    b2[1] = s ? bf[ni].w : bf[ni].y;
#pragma unroll
                    for (int mi = 0; mi < 2; mi++)
                        mma_tf32(acc[mi][ni], a[mi], b2);
                }
            }
        }
        __syncthreads();
    }
}

// ---------------------------------------------------------------------------
// Kernel 1: QKV projection. Q pre-scaled by 0.125*log2(e) (softmax in exp2
// domain), single RNA rounding after scale.
// ---------------------------------------------------------------------------
#define QSCALE 0.18033688011112042f   // 0.125 * log2(e)

__global__ __launch_bounds__(256, 2)
void qkv_tc_kernel(const float* __restrict__ bq, const float* __restrict__ bk,
                   const float* __restrict__ bv)
{
    extern __shared__ float sm[];
    const int sel = blockIdx.z;
    const float* X    = g_x  + (size_t)sel * MTOT * DMODEL;
    const float* bias = (sel == 0) ? bq : (sel == 1) ? bk : bv;
    const float* Bt   = g_wt + (size_t)sel * DMODEL * DMODEL;

    const int rowBase = blockIdx.y * 128;
    const int colBase = blockIdx.x * 128;

    float acc[2][8][4];
#pragma unroll
    for (int mi = 0; mi < 2; mi++)
#pragma unroll
        for (int ni = 0; ni < 8; ni++)
#pragma unroll
            for (int e = 0; e < 4; e++) acc[mi][ni][e] = 0.f;

    gemm_tc_body(X + (size_t)rowBase * DMODEL, Bt + (size_t)colBase * DMODEL, sm, acc);

    const int t = threadIdx.x, lane = t & 31, wid = t >> 5;
    const int gid = lane >> 2, tig = lane & 3;
    const int wM = wid >> 1, wN = wid & 1;
    const float scl = (sel == 0) ? QSCALE : 1.0f;

#pragma unroll
    for (int mi = 0; mi < 2; mi++)
#pragma unroll
        for (int hh = 0; hh < 2; hh++) {
            const int r = rowBase + wM * 32 + mi * 16 + hh * 8 + gid;
            const int b = r >> 11, s = r & 2047;
#pragma unroll
            for (int ni = 0; ni < 8; ni++) {
                const int n = colBase + wN * 64 + ni * 8 + tig * 2;   // even
                const float v0 = tf32r((acc[mi][ni][hh * 2 + 0] + bias[n + 0]) * scl);
                const float v1 = tf32r((acc[mi][ni][hh * 2 + 1] + bias[n + 1]) * scl);
                const int h = n >> 6, d = n & 63;
                if (sel == 2) {
                    float* vt = g_vt + (size_t)(b * NH + h) * DHEAD * SEQ;
                    const int sp = (s & ~15) | perm16(s & 15);
                    vt[(size_t)d * SEQ + sp]       = v0;
                    vt[(size_t)(d + 1) * SEQ + sp] = v1;
                } else {
                    float* dst = ((sel == 0) ? g_q : g_k) +
                        ((size_t)(b * NH + h) * SEQ + s) * DHEAD;
                    const int p0 = perm16(d & 15);
                    dst[(d & ~15) + p0]     = v0;
                    dst[(d & ~15) + p0 + 4] = v1;
                }
            }
        }
}

// ---------------------------------------------------------------------------
// Kernel 2: flash attention. grid(16,64), block 256 (8 warps x 16 q-rows).
// Bit-packed mask: one uint2 (64 key-bits) per row per tile, loaded BEFORE
// the S-mma so its latency is fully covered. Softmax in exp2 domain.
// smem floats: Qs 10240 | Ks 2x5120 | Vs 2x5120 = 122880 B
// ---------------------------------------------------------------------------
#define ATTN_SMEM_BYTES (30720 * 4)   // 122880

__global__ __launch_bounds__(256, 1)
void flash_tc_kernel()
{
    extern __shared__ float sm[];
    float* Qs = sm;               // 128 rows
    float* Ks = sm + 10240;       // 2 x 64 keys
    float* Vs = sm + 20480;       // 2 x 64 d-rows (of Vt)

    const int t = threadIdx.x, lane = t & 31, wid = t >> 5;   // wid 0..7
    const int gid = lane >> 2, tig = lane & 3;

    const int bh = blockIdx.y;
    const int b = bh >> 4, h = bh & 15;
    const int q0 = blockIdx.x * 128;

    const float* Qg = g_q  + ((size_t)bh * SEQ + q0) * DHEAD;
    const float* Kg = g_k  + (size_t)bh * SEQ * DHEAD;
    const float* Vt = g_vt + (size_t)bh * DHEAD * SEQ;

    // per-thread mask row pointers (uint2 = 64 key-bits per tile)
    const uint2* mrow0 = (const uint2*)(g_mbits +
        (size_t)(b * SEQ + q0 + wid * 16 + 0 + gid) * (SEQ / 32));
    const uint2* mrow1 = (const uint2*)(g_mbits +
        (size_t)(b * SEQ + q0 + wid * 16 + 8 + gid) * (SEQ / 32));

    auto stageKV = [&](int kt, float* Kb, float* Vb) {
        const int kb2 = kt * 64;
#pragma unroll
        for (int r = 0; r < 4; r++) {
            const int i = t + r * 256;
            const int a = i >> 4, c = i & 15;
            const int off = (a * 4 + (c >> 2)) * 20 + (c & 3) * 4;
            cp16(smem_u32(Kb + off), Kg + (size_t)(kb2 + a) * DHEAD + c * 4);
            cp16(smem_u32(Vb + off), Vt + (size_t)a * SEQ + kb2 + c * 4);
        }
        CP_COMMIT();
    };

#pragma unroll
    for (int r = 0; r < 8; r++) {
        const int i = t + r * 256;
        const int m = i >> 4, c = i & 15;
        cp16(smem_u32(Qs + (m * 4 + (c >> 2)) * 20 + (c & 3) * 4),
             Qg + (size_t)m * DHEAD + c * 4);
    }
    stageKV(0, Ks, Vs);

    float Ot[8][4], mrowv[2], lrow[2];
#pragma unroll
    for (int nd = 0; nd < 8; nd++)
#pragma unroll
        for (int e = 0; e < 4; e++) Ot[nd][e] = 0.f;
    mrowv[0] = mrowv[1] = -1e30f;
    lrow[0] = lrow[1] = 0.f;

    const int s0lane = 4 * gid + (tig >> 1);
    const int s2lane = s0lane + 2;
    const bool podd = (tig & 1);

    for (int kt = 0; kt < SEQ / 64; kt++) {
        // mask bits for this tile: issued ~2000 cyc before use
        const uint2 mwA = mrow0[kt];
        const uint2 mwB = mrow1[kt];

        float* Kb = Ks + (kt & 1) * 5120;
        float* Vb = Vs + (kt & 1) * 5120;
        if (kt + 1 < SEQ / 64) {
            stageKV(kt + 1, Ks + ((kt + 1) & 1) * 5120, Vs + ((kt + 1) & 1) * 5120);
            CP_WAIT1();
        } else {
            CP_WAIT0();
        }
        __syncthreads();

        // ---- S = Q K^T : warp tile 16 rows x 64 keys ----
        float Sc[8][4];
#pragma unroll
        for (int ni = 0; ni < 8; ni++)
#pragma unroll
            for (int e = 0; e < 4; e++) Sc[ni][e] = 0.f;

#pragma unroll
        for (int g = 0; g < 4; g++) {
            const int r0 = wid * 16 + gid;
            float4 alo = *(const float4*)(Qs + (r0 * 4 + g) * 20 + tig * 4);
            float4 ahi = *(const float4*)(Qs + ((r0 + 8) * 4 + g) * 20 + tig * 4);
            float4 bf[8];
#pragma unroll
            for (int ni = 0; ni < 8; ni++) {
                const int n = ni * 8 + gid;
                bf[ni] = *(const float4*)(Kb + (n * 4 + g) * 20 + tig * 4);
            }
#pragma unroll
            for (int s = 0; s < 2; s++) {
                float a[4];
                a[0] = s ? alo.z : alo.x;
                a[1] = s ? ahi.z : ahi.x;
                a[2] = s ? alo.w : alo.y;
                a[3] = s ? ahi.w : ahi.y;
#pragma unroll
                for (int ni = 0; ni < 8; ni++) {
                    float b2[2];
                    b2[0] = s ? bf[ni].z : bf[ni].x;
                    b2[1] = s ? bf[ni].w : bf[ni].y;
                    mma_tf32(Sc[ni], a, b2);
                }
            }
        }

        // ---- mask (register bits) + online softmax (exp2 domain) ----
#pragma unroll
        for (int hh = 0; hh < 2; hh++) {
            const uint2 mw = hh ? mwB : mwA;
            float sv[8][2];
            float mx = -1e30f;
#pragma unroll
            for (int ni = 0; ni < 8; ni++) {
                const uint32_t w = (ni < 4) ? mw.x : mw.y;
                const int sh = ((ni * 8) & 31) + tig * 2;
                const uint32_t b2 = (w >> sh) & 3u;
                const float s0 = (b2 & 1u) ? Sc[ni][hh * 2 + 0] : -1e9f;
                const float s1 = (b2 & 2u) ? Sc[ni][hh * 2 + 1] : -1e9f;
                sv[ni][0] = s0; sv[ni][1] = s1;
                mx = fmaxf(mx, fmaxf(s0, s1));
            }
            mx = fmaxf(mx, __shfl_xor_sync(0xffffffffu, mx, 1));
            mx = fmaxf(mx, __shfl_xor_sync(0xffffffffu, mx, 2));

            const float mold = mrowv[hh];
            const float mnew = fmaxf(mold, mx);
            const float corr = ex2f(mold - mnew);
            float sum = 0.f;
#pragma unroll
            for (int ni = 0; ni < 8; ni++) {
                const float p0 = ex2f(sv[ni][0] - mnew);
                const float p1 = ex2f(sv[ni][1] - mnew);
                sum += p0 + p1;
                Sc[ni][hh * 2 + 0] = tf32r(p0);
                Sc[ni][hh * 2 + 1] = tf32r(p1);
            }
            sum += __shfl_xor_sync(0xffffffffu, sum, 1);
            sum += __shfl_xor_sync(0xffffffffu, sum, 2);
            lrow[hh] = lrow[hh] * corr + sum;
            mrowv[hh] = mnew;
#pragma unroll
            for (int nd = 0; nd < 8; nd++) {
                Ot[nd][hh * 2 + 0] *= corr;
                Ot[nd][hh * 2 + 1] *= corr;
            }
        }

        // ---- O += P V : P C-frags -> A-frags via shuffles ----
#pragma unroll
        for (int g = 0; g < 4; g++) {
            float4 bf[8];
#pragma unroll
            for (int nd = 0; nd < 8; nd++) {
                const int n = nd * 8 + gid;
                bf[nd] = *(const float4*)(Vb + (n * 4 + g) * 20 + tig * 4);
            }
#pragma unroll
            for (int s = 0; s < 2; s++) {
                const int kk = g * 2 + s;
                float a[4];
                {
                    const float x00 = __shfl_sync(0xffffffffu, Sc[kk][0], s0lane);
                    const float x01 = __shfl_sync(0xffffffffu, Sc[kk][1], s0lane);
                    const float x20 = __shfl_sync(0xffffffffu, Sc[kk][0], s2lane);
                    const float x21 = __shfl_sync(0xffffffffu, Sc[kk][1], s2lane);
                    a[0] = podd ? x01 : x00;
                    a[2] = podd ? x21 : x20;
                    const float y00 = __shfl_sync(0xffffffffu, Sc[kk][2], s0lane);
                    const float y01 = __shfl_sync(0xffffffffu, Sc[kk][3], s0lane);
                    const float y20 = __shfl_sync(0xffffffffu, Sc[kk][2], s2lane);
                    const float y21 = __shfl_sync(0xffffffffu, Sc[kk][3], s2lane);
                    a[1] = podd ? y01 : y00;
                    a[3] = podd ? y21 : y20;
                }
#pragma unroll
                for (int nd = 0; nd < 8; nd++) {
                    float b2[2];
                    b2[0] = s ? bf[nd].z : bf[nd].x;
                    b2[1] = s ? bf[nd].w : bf[nd].y;
                    mma_tf32(Ot[nd], a, b2);
                }
            }
        }
        __syncthreads();
    }

    // ---- normalize + write tf32-rounded, D-permuted, to g_attn ----
#pragma unroll
    for (int hh = 0; hh < 2; hh++) {
        const int rloc = wid * 16 + hh * 8 + gid;
        const int grow = q0 + rloc;
        const float inv = 1.0f / lrow[hh];
        float* op = g_attn + ((size_t)b * SEQ + grow) * DMODEL + h * DHEAD;
#pragma unroll
        for (int nd = 0; nd < 8; nd++) {
            const int d = nd * 8 + tig * 2;
            const int p0 = perm16(d & 15);
            op[(d & ~15) + p0]     = tf32r(Ot[nd][hh * 2 + 0] * inv);
            op[(d & ~15) + p0 + 4] = tf32r(Ot[nd][hh * 2 + 1] * inv);
        }
    }
}

// ---------------------------------------------------------------------------
// Kernel 3: output projection. fp32 out.
// ---------------------------------------------------------------------------
__global__ __launch_bounds__(256, 2)
void out_tc_kernel(const float* __restrict__ bo, float* __restrict__ out)
{
    extern __shared__ float sm[];
    const float* Bt = g_wt + 3ull * DMODEL * DMODEL;
    const int rowBase = blockIdx.y * 128;
    const int colBase = blockIdx.x * 128;

    float acc[2][8][4];
#pragma unroll
    for (int mi = 0; mi < 2; mi++)
#pragma unroll
        for (int ni = 0; ni < 8; ni++)
#pragma unroll
            for (int e = 0; e < 4; e++) acc[mi][ni][e] = 0.f;

    gemm_tc_body(g_attn + (size_t)rowBase * DMODEL, Bt + (size_t)colBase * DMODEL, sm, acc);

    const int t = threadIdx.x, lane = t & 31, wid = t >> 5;
    const int gid = lane >> 2, tig = lane & 3;
    const int wM = wid >> 1, wN = wid & 1;

#pragma unroll
    for (int mi = 0; mi < 2; mi++)
#pragma unroll
        for (int hh = 0; hh < 2; hh++) {
            const int r = rowBase + wM * 32 + mi * 16 + hh * 8 + gid;
#pragma unroll
            for (int ni = 0; ni < 8; ni++) {
                const int n = colBase + wN * 64 + ni * 8 + tig * 2;
                *(float2*)(out + (size_t)r * DMODEL + n) =
                    make_float2(acc[mi][ni][hh * 2 + 0] + bo[n + 0],
                                acc[mi][ni][hh * 2 + 1] + bo[n + 1]);
            }
        }
}

// ---------------------------------------------------------------------------
extern "C" void kernel_launch(void* const* d_in, const int* in_sizes, int n_in,
                              void* d_out, int out_size)
{
    (void)in_sizes; (void)n_in; (void)out_size;
    const float* q_in = (const float*)d_in[0];
    const float* k_in = (const float*)d_in[1];
    const float* v_in = (const float*)d_in[2];
    const int*   mask = (const int*)d_in[3];
    const float* Wq = (const float*)d_in[4];
    const float* bq = (const float*)d_in[5];
    const float* Wk = (const float*)d_in[6];
    const float* bk = (const float*)d_in[7];
    const float* Wv = (const float*)d_in[8];
    const float* bv = (const float*)d_in[9];
    const float* Wo = (const float*)d_in[10];
    const float* bo = (const float*)d_in[11];
    float* out = (float*)d_out;

    cudaFuncSetAttribute(qkv_tc_kernel,
        cudaFuncAttributeMaxDynamicSharedMemorySize, GEMM_SMEM_BYTES);
    cudaFuncSetAttribute(out_tc_kernel,
        cudaFuncAttributeMaxDynamicSharedMemorySize, GEMM_SMEM_BYTES);
    cudaFuncSetAttribute(flash_tc_kernel,
        cudaFuncAttributeMaxDynamicSharedMemorySize, ATTN_SMEM_BYTES);

    pack_mask<<<(NUM_B * SEQ * (SEQ / 32)) / 256, 256>>>(mask);
    round_perm_x<<<dim3(MTOT * DMODEL / 16 / 256, 3), 256>>>(q_in, k_in, v_in);
    transpose_weights<<<dim3(32, 32, 4), dim3(32, 8)>>>(Wq, Wk, Wv, Wo);

    dim3 gP(DMODEL / 128, MTOT / 128, 3);
    qkv_tc_kernel<<<gP, 256, GEMM_SMEM_BYTES>>>(bq, bk, bv);

    dim3 gA(SEQ / 128, NUM_B * NH);
    flash_tc_kernel<<<gA, 256, ATTN_SMEM_BYTES>>>();

    dim3 gO(DMODEL / 128, MTOT / 128);
    out_tc_kernel<<<gO, 256, GEMM_SMEM_BYTES>>>(bo, out);
}

// round 17
// speedup vs baseline: 1.3591x; 1.3591x over previous
#include <cuda_runtime.h>
#include <cstdint>

#define NUM_B  4
#define SEQ    2048
#define DMODEL 1024
#define NH     16
#define DHEAD  64
#define MTOT   (NUM_B * SEQ)   // 8192

// ---------------------------------------------------------------------------
// Scratch (__device__ globals). All tf32-pre-rounded AND k-dim pre-permuted
// (within each 16-chunk: pos p holds k = perm(p), perm(p)=((p&3)<<2)|(p>>2)).
// Gmem is byte-identical to the smem tile layout -> staging is cp.async 16B,
// and flash's Q fragments load straight from gmem into registers.
// ---------------------------------------------------------------------------
__device__ float g_q   [(size_t)NUM_B * NH * SEQ * DHEAD];   // [bh][s][d~] (x0.125)
__device__ float g_k   [(size_t)NUM_B * NH * SEQ * DHEAD];   // [bh][s][d~]
__device__ float g_vt  [(size_t)NUM_B * NH * DHEAD * SEQ];   // [bh][d][s~]
__device__ float g_attn[(size_t)NUM_B * SEQ * DMODEL];       // [b][s][D~]
__device__ float g_wt  [4ull * DMODEL * DMODEL];             // Wt[z][n][k~]
__device__ float g_x   [3ull * MTOT * DMODEL];               // x rounded+perm

// ---------------------------------------------------------------------------
__device__ __forceinline__ float tf32r(float x) {
    uint32_t u;
    asm("cvt.rna.tf32.f32 %0, %1;" : "=r"(u) : "f"(x));
    return __uint_as_float(u);
}
__device__ __forceinline__ int perm16(int v) { return ((v & 3) << 2) | (v >> 2); }

__device__ __forceinline__ void mma_tf32(float c[4], const float a[4], const float b[2]) {
    const uint32_t* A = reinterpret_cast<const uint32_t*>(a);
    const uint32_t* B = reinterpret_cast<const uint32_t*>(b);
    asm volatile(
        "mma.sync.aligned.m16n8k8.row.col.f32.tf32.tf32.f32 "
        "{%0,%1,%2,%3},{%4,%5,%6,%7},{%8,%9},{%0,%1,%2,%3};\n"
        : "+f"(c[0]), "+f"(c[1]), "+f"(c[2]), "+f"(c[3])
        : "r"(A[0]), "r"(A[1]), "r"(A[2]), "r"(A[3]), "r"(B[0]), "r"(B[1]));
}

__device__ __forceinline__ uint32_t smem_u32(const void* p) {
    return (uint32_t)__cvta_generic_to_shared(p);
}
__device__ __forceinline__ void cp16(uint32_t dst, const void* src) {
    asm volatile("cp.async.cg.shared.global [%0], [%1], 16;" :: "r"(dst), "l"(src));
}
#define CP_COMMIT() asm volatile("cp.async.commit_group;" ::: "memory")
#define CP_WAIT1()  asm volatile("cp.async.wait_group 1;" ::: "memory")
#define CP_WAIT0()  asm volatile("cp.async.wait_group 0;" ::: "memory")

// ---------------------------------------------------------------------------
// Pre-round + permute inputs: per 16-chunk transpose of 4 float4s.
// ---------------------------------------------------------------------------
__global__ void round_perm_x(const float* __restrict__ xq,
                             const float* __restrict__ xk,
                             const float* __restrict__ xv)
{
    const int z = blockIdx.y;
    const float* src = (z == 0) ? xq : (z == 1) ? xk : xv;
    float* dst = g_x + (size_t)z * MTOT * DMODEL;
    const size_t chunk = (size_t)blockIdx.x * blockDim.x + threadIdx.x;
    const float4* s = (const float4*)src + chunk * 4;
    float4 i0 = s[0], i1 = s[1], i2 = s[2], i3 = s[3];
    float4* d = (float4*)dst + chunk * 4;
    d[0] = make_float4(tf32r(i0.x), tf32r(i1.x), tf32r(i2.x), tf32r(i3.x));
    d[1] = make_float4(tf32r(i0.y), tf32r(i1.y), tf32r(i2.y), tf32r(i3.y));
    d[2] = make_float4(tf32r(i0.z), tf32r(i1.z), tf32r(i2.z), tf32r(i3.z));
    d[3] = make_float4(tf32r(i0.w), tf32r(i1.w), tf32r(i2.w), tf32r(i3.w));
}

// ---------------------------------------------------------------------------
// Weight transpose + round + k-permute: g_wt[z][n][kpos] = tf32(W[perm(kpos)][n]).
// ---------------------------------------------------------------------------
__global__ void transpose_weights(const float* __restrict__ Wq, const float* __restrict__ Wk,
                                  const float* __restrict__ Wv, const float* __restrict__ Wo)
{
    __shared__ float tile[32][33];
    const float* W = (blockIdx.z == 0) ? Wq : (blockIdx.z == 1) ? Wk
                   : (blockIdx.z == 2) ? Wv : Wo;
    float* Wt = g_wt + (size_t)blockIdx.z * DMODEL * DMODEL;
    const int x0 = blockIdx.x * 32, y0 = blockIdx.y * 32;
    const int tx = threadIdx.x, ty = threadIdx.y;
#pragma unroll
    for (int r = 0; r < 32; r += 8)
        tile[ty + r][tx] = W[(size_t)(y0 + ty + r) * DMODEL + x0 + tx];
    __syncthreads();
    const int kl = (tx & ~15) | perm16(tx & 15);
#pragma unroll
    for (int r = 0; r < 32; r += 8)
        Wt[(size_t)(x0 + ty + r) * DMODEL + y0 + tx] = tf32r(tile[kl][ty + r]);
}

// ---------------------------------------------------------------------------
// tf32 GEMM mainloop (cp.async, double-buffered). Proven R14/R15.
// ---------------------------------------------------------------------------
#define GEMM_SMEM_BYTES (2 * 2 * 256 * 24 * 4)   // 98304

__device__ __forceinline__ void gemm_tc_body(
    const float* __restrict__ Ablk, const float* __restrict__ Btblk,
    float* sm, float (&acc)[2][8][4])
{
    const int t = threadIdx.x, lane = t & 31, wid = t >> 5;
    const int gid = lane >> 2, tig = lane & 3;
    const int wM = wid >> 1, wN = wid & 1;

    auto stage = [&](int k0, int buf) {
        float* As = sm + buf * 12288;
        float* Bs = As + 6144;
#pragma unroll
        for (int r = 0; r < 4; r++) {
            const int i = t + r * 256;
            const int m = i >> 3, kq = i & 7;
            const int off = (m * 2 + (kq >> 2)) * 24 + (kq & 3) * 4;
            cp16(smem_u32(As + off), Ablk  + (size_t)m * DMODEL + k0 + kq * 4);
            cp16(smem_u32(Bs + off), Btblk + (size_t)m * DMODEL + k0 + kq * 4);
        }
        CP_COMMIT();
    };
    stage(0, 0);

    for (int k0 = 0; k0 < DMODEL; k0 += 32) {
        const int buf = (k0 >> 5) & 1;
        if (k0 + 32 < DMODEL) { stage(k0 + 32, buf ^ 1); CP_WAIT1(); }
        else                  { CP_WAIT0(); }
        __syncthreads();

        float* As = sm + buf * 12288;
        float* Bs = As + 6144;
#pragma unroll
        for (int g = 0; g < 2; g++) {
            float4 alo[2], ahi[2], bf[8];
#pragma unroll
            for (int mi = 0; mi < 2; mi++) {
                const int r0 = wM * 32 + mi * 16 + gid;
                alo[mi] = *(const float4*)(As + (r0 * 2 + g) * 24 + tig * 4);
                ahi[mi] = *(const float4*)(As + ((r0 + 8) * 2 + g) * 24 + tig * 4);
            }
#pragma unroll
            for (int ni = 0; ni < 8; ni++) {
                const int n = wN * 64 + ni * 8 + gid;
                bf[ni] = *(const float4*)(Bs + (n * 2 + g) * 24 + tig * 4);
            }
#pragma unroll
            for (int s = 0; s < 2; s++) {
                float a[2][4];
#pragma unroll
                for (int mi = 0; mi < 2; mi++) {
                    a[mi][0] = s ? alo[mi].z : alo[mi].x;
                    a[mi][1] = s ? ahi[mi].z : ahi[mi].x;
                    a[mi][2] = s ? alo[mi].w : alo[mi].y;
                    a[mi][3] = s ? ahi[mi].w : ahi[mi].y;
                }
#pragma unroll
                for (int ni = 0; ni < 8; ni++) {
                    float b2[2];
                    b2[0] = s ? bf[ni].z : bf[ni].x;
                    b2[1] = s ? bf[ni].w : bf[ni].y;
#pragma unroll
                    for (int mi = 0; mi < 2; mi++)
                        mma_tf32(acc[mi][ni], a[mi], b2);
                }
            }
        }
        __syncthreads();
    }
}

// ---------------------------------------------------------------------------
// Kernel 1: QKV projection. grid(8,64,3), block 256, 2 CTAs/SM.
// Outputs tf32-rounded + permuted; Q pre-scaled by exact pow2 1/8 AFTER round.
// ---------------------------------------------------------------------------
__global__ __launch_bounds__(256, 2)
void qkv_tc_kernel(const float* __restrict__ bq, const float* __restrict__ bk,
                   const float* __restrict__ bv)
{
    extern __shared__ float sm[];
    const int sel = blockIdx.z;
    const float* X    = g_x  + (size_t)sel * MTOT * DMODEL;
    const float* bias = (sel == 0) ? bq : (sel == 1) ? bk : bv;
    const float* Bt   = g_wt + (size_t)sel * DMODEL * DMODEL;

    const int rowBase = blockIdx.y * 128;
    const int colBase = blockIdx.x * 128;

    float acc[2][8][4];
#pragma unroll
    for (int mi = 0; mi < 2; mi++)
#pragma unroll
        for (int ni = 0; ni < 8; ni++)
#pragma unroll
            for (int e = 0; e < 4; e++) acc[mi][ni][e] = 0.f;

    gemm_tc_body(X + (size_t)rowBase * DMODEL, Bt + (size_t)colBase * DMODEL, sm, acc);

    const int t = threadIdx.x, lane = t & 31, wid = t >> 5;
    const int gid = lane >> 2, tig = lane & 3;
    const int wM = wid >> 1, wN = wid & 1;
    const float scl = (sel == 0) ? 0.125f : 1.0f;

#pragma unroll
    for (int mi = 0; mi < 2; mi++)
#pragma unroll
        for (int hh = 0; hh < 2; hh++) {
            const int r = rowBase + wM * 32 + mi * 16 + hh * 8 + gid;
            const int b = r >> 11, s = r & 2047;
#pragma unroll
            for (int ni = 0; ni < 8; ni++) {
                const int n = colBase + wN * 64 + ni * 8 + tig * 2;   // even
                const float v0 = tf32r(acc[mi][ni][hh * 2 + 0] + bias[n + 0]) * scl;
                const float v1 = tf32r(acc[mi][ni][hh * 2 + 1] + bias[n + 1]) * scl;
                const int h = n >> 6, d = n & 63;
                if (sel == 2) {
                    float* vt = g_vt + (size_t)(b * NH + h) * DHEAD * SEQ;
                    const int sp = (s & ~15) | perm16(s & 15);
                    vt[(size_t)d * SEQ + sp]       = v0;
                    vt[(size_t)(d + 1) * SEQ + sp] = v1;
                } else {
                    float* dst = ((sel == 0) ? g_q : g_k) +
                        ((size_t)(b * NH + h) * SEQ + s) * DHEAD;
                    const int p0 = perm16(d & 15);
                    dst[(d & ~15) + p0]     = v0;
                    dst[(d & ~15) + p0 + 4] = v1;
                }
            }
        }
}

// ---------------------------------------------------------------------------
// Kernel 2: flash attention. grid(16,64), block 256 (8 warps x 16 q-rows).
// NEW vs R15: Q fragments live in registers (loaded once, straight from gmem
// -- fragment order matches the pre-permuted layout), Qs smem deleted.
// K/V cp.async double-buffered; P in registers via shuffle C->A; mask int2
// loads with L2 prefetch (proven R13/R15 path).
// smem floats: Ks 2x5120 | Vs 2x5120 = 81920 B
// ---------------------------------------------------------------------------
#define ATTN_SMEM_BYTES (20480 * 4)   // 81920

__global__ __launch_bounds__(256, 1)
void flash_tc_kernel(const int* __restrict__ mask)
{
    extern __shared__ float sm[];
    float* Ks = sm;               // 2 x 64 keys
    float* Vs = sm + 10240;       // 2 x 64 d-rows (of Vt)

    const int t = threadIdx.x, lane = t & 31, wid = t >> 5;   // wid 0..7
    const int gid = lane >> 2, tig = lane & 3;

    const int bh = blockIdx.y;
    const int b = bh >> 4, h = bh & 15;
    const int q0 = blockIdx.x * 128;

    const float* Qg = g_q  + ((size_t)bh * SEQ + q0) * DHEAD;
    const float* Kg = g_k  + (size_t)bh * SEQ * DHEAD;
    const float* Vt = g_vt + (size_t)bh * DHEAD * SEQ;
    const int* maskBase = mask + ((size_t)b * SEQ + q0) * SEQ;

    auto stageKV = [&](int kt, float* Kb, float* Vb) {
        const int kb2 = kt * 64;
#pragma unroll
        for (int r = 0; r < 4; r++) {
            const int i = t + r * 256;
            const int a = i >> 4, c = i & 15;
            const int off = (a * 4 + (c >> 2)) * 20 + (c & 3) * 4;
            cp16(smem_u32(Kb + off), Kg + (size_t)(kb2 + a) * DHEAD + c * 4);
            cp16(smem_u32(Vb + off), Vt + (size_t)a * SEQ + kb2 + c * 4);
        }
        CP_COMMIT();
    };
    stageKV(0, Ks, Vs);

    // Q fragments for this warp's 16 rows, direct from gmem (kt-invariant).
    // A-frag (g): lane(gid,tig) needs rows r0,r0+8 at d-positions g*16+tig*4..+3
    // (pre-permuted layout) = float4 index (g*4+tig) of each row.
    const int r0 = wid * 16 + gid;
    float4 qlo[4], qhi[4];
#pragma unroll
    for (int g = 0; g < 4; g++) {
        qlo[g] = *(const float4*)(Qg + (size_t)r0 * DHEAD + (g * 4 + tig) * 4);
        qhi[g] = *(const float4*)(Qg + (size_t)(r0 + 8) * DHEAD + (g * 4 + tig) * 4);
    }

    float Ot[8][4], mrow[2], lrow[2];
#pragma unroll
    for (int nd = 0; nd < 8; nd++)
#pragma unroll
        for (int e = 0; e < 4; e++) Ot[nd][e] = 0.f;
    mrow[0] = mrow[1] = -1e30f;
    lrow[0] = lrow[1] = 0.f;

    const int s0lane = 4 * gid + (tig >> 1);
    const int s2lane = s0lane + 2;
    const bool podd = (tig & 1);

    for (int kt = 0; kt < SEQ / 64; kt++) {
        {
            const int* pa = maskBase + (size_t)(t >> 1) * SEQ + kt * 64 + (t & 1) * 32;
            asm volatile("prefetch.global.L2 [%0];" :: "l"(pa));
        }
        float* Kb = Ks + (kt & 1) * 5120;
        float* Vb = Vs + (kt & 1) * 5120;
        if (kt + 1 < SEQ / 64) {
            stageKV(kt + 1, Ks + ((kt + 1) & 1) * 5120, Vs + ((kt + 1) & 1) * 5120);
            CP_WAIT1();
        } else {
            CP_WAIT0();
        }
        __syncthreads();

        // ---- S = Q K^T : warp tile 16 rows x 64 keys, Q from registers ----
        float Sc[8][4];
#pragma unroll
        for (int ni = 0; ni < 8; ni++)
#pragma unroll
            for (int e = 0; e < 4; e++) Sc[ni][e] = 0.f;

#pragma unroll
        for (int g = 0; g < 4; g++) {
            float4 bf[8];
#pragma unroll
            for (int ni = 0; ni < 8; ni++) {
                const int n = ni * 8 + gid;
                bf[ni] = *(const float4*)(Kb + (n * 4 + g) * 20 + tig * 4);
            }
#pragma unroll
            for (int s = 0; s < 2; s++) {
                float a[4];
                a[0] = s ? qlo[g].z : qlo[g].x;
                a[1] = s ? qhi[g].z : qhi[g].x;
                a[2] = s ? qlo[g].w : qlo[g].y;
                a[3] = s ? qhi[g].w : qhi[g].y;
#pragma unroll
                for (int ni = 0; ni < 8; ni++) {
                    float b2[2];
                    b2[0] = s ? bf[ni].z : bf[ni].x;
                    b2[1] = s ? bf[ni].w : bf[ni].y;
                    mma_tf32(Sc[ni], a, b2);
                }
            }
        }

        // ---- mask + online softmax; P overwrites Sc (tf32-rounded) ----
        const int kb = kt * 64;
#pragma unroll
        for (int hh = 0; hh < 2; hh++) {
            const int rloc = wid * 16 + hh * 8 + gid;
            const int* mp = maskBase + (size_t)rloc * SEQ + kb;
            float sv[8][2];
            float mx = -1e30f;
#pragma unroll
            for (int ni = 0; ni < 8; ni++) {
                const int2 mv = *(const int2*)(mp + ni * 8 + tig * 2);
                const float s0 = (mv.x == 0) ? -1e9f : Sc[ni][hh * 2 + 0];
                const float s1 = (mv.y == 0) ? -1e9f : Sc[ni][hh * 2 + 1];
                sv[ni][0] = s0; sv[ni][1] = s1;
                mx = fmaxf(mx, fmaxf(s0, s1));
            }
            mx = fmaxf(mx, __shfl_xor_sync(0xffffffffu, mx, 1));
            mx = fmaxf(mx, __shfl_xor_sync(0xffffffffu, mx, 2));

            const float mold = mrow[hh];
            const float mnew = fmaxf(mold, mx);
            const float corr = __expf(mold - mnew);
            float sum = 0.f;
#pragma unroll
            for (int ni = 0; ni < 8; ni++) {
                const float p0 = __expf(sv[ni][0] - mnew);
                const float p1 = __expf(sv[ni][1] - mnew);
                sum += p0 + p1;
                Sc[ni][hh * 2 + 0] = tf32r(p0);
                Sc[ni][hh * 2 + 1] = tf32r(p1);
            }
            sum += __shfl_xor_sync(0xffffffffu, sum, 1);
            sum += __shfl_xor_sync(0xffffffffu, sum, 2);
            lrow[hh] = lrow[hh] * corr + sum;
            mrow[hh] = mnew;
#pragma unroll
            for (int nd = 0; nd < 8; nd++) {
                Ot[nd][hh * 2 + 0] *= corr;
                Ot[nd][hh * 2 + 1] *= corr;
            }
        }

        // ---- O += P V : P C-frags -> A-frags via shuffles; V from smem ----
#pragma unroll
        for (int g = 0; g < 4; g++) {
            float4 bf[8];
#pragma unroll
            for (int nd = 0; nd < 8; nd++) {
                const int n = nd * 8 + gid;
                bf[nd] = *(const float4*)(Vb + (n * 4 + g) * 20 + tig * 4);
            }
#pragma unroll
            for (int s = 0; s < 2; s++) {
                const int kk = g * 2 + s;
                float a[4];
                {
                    const float x00 = __shfl_sync(0xffffffffu, Sc[kk][0], s0lane);
                    const float x01 = __shfl_sync(0xffffffffu, Sc[kk][1], s0lane);
                    const float x20 = __shfl_sync(0xffffffffu, Sc[kk][0], s2lane);
                    const float x21 = __shfl_sync(0xffffffffu, Sc[kk][1], s2lane);
                    a[0] = podd ? x01 : x00;
                    a[2] = podd ? x21 : x20;
                    const float y00 = __shfl_sync(0xffffffffu, Sc[kk][2], s0lane);
                    const float y01 = __shfl_sync(0xffffffffu, Sc[kk][3], s0lane);
                    const float y20 = __shfl_sync(0xffffffffu, Sc[kk][2], s2lane);
                    const float y21 = __shfl_sync(0xffffffffu, Sc[kk][3], s2lane);
                    a[1] = podd ? y01 : y00;
                    a[3] = podd ? y21 : y20;
                }
#pragma unroll
                for (int nd = 0; nd < 8; nd++) {
                    float b2[2];
                    b2[0] = s ? bf[nd].z : bf[nd].x;
                    b2[1] = s ? bf[nd].w : bf[nd].y;
                    mma_tf32(Ot[nd], a, b2);
                }
            }
        }
        __syncthreads();
    }

    // ---- normalize + write tf32-rounded, D-permuted, to g_attn ----
#pragma unroll
    for (int hh = 0; hh < 2; hh++) {
        const int rloc = wid * 16 + hh * 8 + gid;
        const int grow = q0 + rloc;
        const float inv = 1.0f / lrow[hh];
        float* op = g_attn + ((size_t)b * SEQ + grow) * DMODEL + h * DHEAD;
#pragma unroll
        for (int nd = 0; nd < 8; nd++) {
            const int d = nd * 8 + tig * 2;
            const int p0 = perm16(d & 15);
            op[(d & ~15) + p0]     = tf32r(Ot[nd][hh * 2 + 0] * inv);
            op[(d & ~15) + p0 + 4] = tf32r(Ot[nd][hh * 2 + 1] * inv);
        }
    }
}

// ---------------------------------------------------------------------------
// Kernel 3: output projection. grid(8,64), block 256, 2 CTAs/SM. fp32 out.
// ---------------------------------------------------------------------------
__global__ __launch_bounds__(256, 2)
void out_tc_kernel(const float* __restrict__ bo, float* __restrict__ out)
{
    extern __shared__ float sm[];
    const float* Bt = g_wt + 3ull * DMODEL * DMODEL;
    const int rowBase = blockIdx.y * 128;
    const int colBase = blockIdx.x * 128;

    float acc[2][8][4];
#pragma unroll
    for (int mi = 0; mi < 2; mi++)
#pragma unroll
        for (int ni = 0; ni < 8; ni++)
#pragma unroll
            for (int e = 0; e < 4; e++) acc[mi][ni][e] = 0.f;

    gemm_tc_body(g_attn + (size_t)rowBase * DMODEL, Bt + (size_t)colBase * DMODEL, sm, acc);

    const int t = threadIdx.x, lane = t & 31, wid = t >> 5;
    const int gid = lane >> 2, tig = lane & 3;
    const int wM = wid >> 1, wN = wid & 1;

#pragma unroll
    for (int mi = 0; mi < 2; mi++)
#pragma unroll
        for (int hh = 0; hh < 2; hh++) {
            const int r = rowBase + wM * 32 + mi * 16 + hh * 8 + gid;
#pragma unroll
            for (int ni = 0; ni < 8; ni++) {
                const int n = colBase + wN * 64 + ni * 8 + tig * 2;
                *(float2*)(out + (size_t)r * DMODEL + n) =
                    make_float2(acc[mi][ni][hh * 2 + 0] + bo[n + 0],
                                acc[mi][ni][hh * 2 + 1] + bo[n + 1]);
            }
        }
}

// ---------------------------------------------------------------------------
extern "C" void kernel_launch(void* const* d_in, const int* in_sizes, int n_in,
                              void* d_out, int out_size)
{
    (void)in_sizes; (void)n_in; (void)out_size;
    const float* q_in = (const float*)d_in[0];
    const float* k_in = (const float*)d_in[1];
    const float* v_in = (const float*)d_in[2];
    const int*   mask = (const int*)d_in[3];
    const float* Wq = (const float*)d_in[4];
    const float* bq = (const float*)d_in[5];
    const float* Wk = (const float*)d_in[6];
    const float* bk = (const float*)d_in[7];
    const float* Wv = (const float*)d_in[8];
    const float* bv = (const float*)d_in[9];
    const float* Wo = (const float*)d_in[10];
    const float* bo = (const float*)d_in[11];
    float* out = (float*)d_out;

    cudaFuncSetAttribute(qkv_tc_kernel,
        cudaFuncAttributeMaxDynamicSharedMemorySize, GEMM_SMEM_BYTES);
    cudaFuncSetAttribute(out_tc_kernel,
        cudaFuncAttributeMaxDynamicSharedMemorySize, GEMM_SMEM_BYTES);
    cudaFuncSetAttribute(flash_tc_kernel,
        cudaFuncAttributeMaxDynamicSharedMemorySize, ATTN_SMEM_BYTES);

    round_perm_x<<<dim3(MTOT * DMODEL / 16 / 256, 3), 256>>>(q_in, k_in, v_in);
    transpose_weights<<<dim3(32, 32, 4), dim3(32, 8)>>>(Wq, Wk, Wv, Wo);

    dim3 gP(DMODEL / 128, MTOT / 128, 3);
    qkv_tc_kernel<<<gP, 256, GEMM_SMEM_BYTES>>>(bq, bk, bv);

    dim3 gA(SEQ / 128, NUM_B * NH);
    flash_tc_kernel<<<gA, 256, ATTN_SMEM_BYTES>>>(mask);

    dim3 gO(DMODEL / 128, MTOT / 128);
    out_tc_kernel<<<gO, 256, GEMM_SMEM_BYTES>>>(bo, out);
}